// round 16
// baseline (speedup 1.0000x reference)
#include <cuda_runtime.h>

// ---------------------------------------------------------------------------
// Problem constants (fixed shapes per reference setup_inputs)
// ---------------------------------------------------------------------------
namespace {
constexpr int NPTS = 16384;
constexpr int BSZ  = 2;
constexpr int NKP  = 64;
constexpr int FD   = 64;
constexpr int KNN  = 64;
constexpr float RAD2 = 2.25f;   // 1.5^2

// Output layout: concat of flattened (T, D, G, H)
constexpr int SZ_T  = BSZ * NKP * NKP * 16;   // 131072
constexpr int SZ_D  = BSZ * NKP * NKP;        // 8192
constexpr int SZ_G  = BSZ * NKP * FD * 4;     // 32768
constexpr int OFF_T = 0;
constexpr int OFF_D = SZ_T;
constexpr int OFF_G = OFF_D + SZ_D;
constexpr int OFF_H = OFF_G + SZ_G;

constexpr int SEG = NPTS / 8;                 // 2048 points per warp segment
}

// Per-unit Gram matrices (lower triangle, packed 10): units 0..127 = G side,
// 128..255 = H side. Written by moments kernel, read by pair kernel.
__device__ double g_gram[256][10];

// ---------------------------------------------------------------------------
// Kernel 1: fused ball-query + moments + Gram epilogue (R15 logic, with the
// measured-neutral prefetch machinery removed to cut register pressure).
// ---------------------------------------------------------------------------
__global__ void __launch_bounds__(256)
ume_moments_kernel(const float* __restrict__ s_pts, const float* __restrict__ s_ft,
                   const float* __restrict__ s_kp,
                   const float* __restrict__ t_pts, const float* __restrict__ t_ft,
                   const float* __restrict__ t_kp,
                   float* __restrict__ out)
{
    const int side = blockIdx.y;
    const float* pts = side ? t_pts : s_pts;
    const float* ft  = side ? t_ft  : s_ft;
    const float* kp  = side ? t_kp  : s_kp;
    float* gout = out + (side ? OFF_H : OFF_G);

    const int b    = blockIdx.x >> 6;
    const int kk   = blockIdx.x & 63;
    const int tid  = threadIdx.x;
    const int lane = tid & 31;
    const int wid  = tid >> 5;

    const float kx = kp[(b * NKP + kk) * 3 + 0];
    const float ky = kp[(b * NKP + kk) * 3 + 1];
    const float kz = kp[(b * NKP + kk) * 3 + 2];

    __shared__ int    s_wl[8][KNN];    // per-warp ordered hit lists
    __shared__ int    s_wc[8];         // per-warp hit counts (capped at 64)
    __shared__ int    s_idx[KNN];      // merged first-64 (sentinel -1)
    __shared__ float  s_red[256];
    __shared__ float  s_r2[2];
    __shared__ double s_den;
    __shared__ double s_gram2[2][10];

    const float* bp = pts + (size_t)b * NPTS * 3;

    // ---- Phase A: warp-local scan (decoupled ballots, no prefetch) ---------
    {
        const int seg0 = wid * SEG;
        int cnt_w = 0;
        const unsigned lt = (1u << lane) - 1u;
        for (int ch = 0; ch < 8; ++ch) {
            if (cnt_w >= KNN) break;
            float px[8], py[8], pz[8];
            #pragma unroll
            for (int u = 0; u < 8; ++u) {
                const int j = seg0 + ch * 256 + u * 32 + lane;
                px[u] = bp[3 * j + 0];
                py[u] = bp[3 * j + 1];
                pz[u] = bp[3 * j + 2];
            }
            unsigned mm[8];
            unsigned myh = 0u;
            #pragma unroll
            for (int u = 0; u < 8; ++u) {
                const float dx = px[u] - kx, dy = py[u] - ky, dz = pz[u] - kz;
                const bool hit = (dx * dx + dy * dy + dz * dz) < RAD2;
                mm[u] = __ballot_sync(0xffffffffu, hit);
                myh |= (hit ? 1u : 0u) << u;
            }
            #pragma unroll
            for (int u = 0; u < 8; ++u) {
                const int j = seg0 + ch * 256 + u * 32 + lane;
                const int pos = cnt_w + __popc(mm[u] & lt);
                if (((myh >> u) & 1u) && pos < KNN) s_wl[wid][pos] = j;
                cnt_w += __popc(mm[u]);
            }
        }
        if (lane == 0) s_wc[wid] = min(cnt_w, KNN);
    }
    __syncthreads();

    // ---- Merge: ordered concat of warp lists, truncated to 64 --------------
    if (tid < KNN) {
        int pre = 0, total = 0;
        #pragma unroll
        for (int ww = 0; ww < 8; ++ww) total += s_wc[ww];
        const int cnt = min(total, KNN);
        int v = -1;
        if (tid < cnt) {
            #pragma unroll
            for (int ww = 0; ww < 8; ++ww) {
                const int c = s_wc[ww];
                if (tid >= pre && tid < pre + c) v = s_wl[ww][tid - pre];
                pre += c;
            }
        }
        s_idx[tid] = v;
    }
    __syncthreads();

    // ---- Phase B: moments, batched gathers (groups of 8), 4 fp64 chains ----
    const int f = tid >> 2;
    const int c = tid & 3;
    const float* bft = ft + (size_t)b * NPTS * FD;

    double a0 = 0.0, a1 = 0.0, a2 = 0.0, a3 = 0.0;
    #pragma unroll 2
    for (int g = 0; g < 8; ++g) {
        int   id8[8];
        float wv[8], pp[8];
        #pragma unroll
        for (int u = 0; u < 8; ++u) id8[u] = s_idx[g * 8 + u];
        #pragma unroll
        for (int u = 0; u < 8; ++u) {
            const bool valid = id8[u] >= 0;
            const int i0 = valid ? id8[u] : 0;
            wv[u] = valid ? bft[(size_t)i0 * FD + f] : 0.0f;
            pp[u] = (c == 0) ? 1.0f : bp[i0 * 3 + (c - 1)];
        }
        a0 += (double)wv[0] * (double)pp[0];
        a1 += (double)wv[1] * (double)pp[1];
        a2 += (double)wv[2] * (double)pp[2];
        a3 += (double)wv[3] * (double)pp[3];
        a0 += (double)wv[4] * (double)pp[4];
        a1 += (double)wv[5] * (double)pp[5];
        a2 += (double)wv[6] * (double)pp[6];
        a3 += (double)wv[7] * (double)pp[7];
    }
    const double acc = (a0 + a1) + (a2 + a3);

    s_red[tid] = (float)acc;
    __syncthreads();
    if (tid < 64) {
        float v = s_red[tid * 4];          // m0[f] values
        #pragma unroll
        for (int off = 16; off > 0; off >>= 1)
            v += __shfl_xor_sync(0xffffffffu, v, off);
        if ((tid & 31) == 0) s_r2[tid >> 5] = v;
    }
    __syncthreads();
    if (tid == 0) s_den = (double)(s_r2[0] + s_r2[1]) + 1e-6;
    __syncthreads();
    const float vnorm = (float)(acc / s_den);
    gout[((size_t)(b * NKP + kk) * FD + f) * 4 + c] = vnorm;

    // ---- Gram epilogue: Pg (or Ph) for this unit, exact fp64 products ------
    s_red[tid] = vnorm;                    // stage normalized row values
    __syncthreads();
    if (tid < 64) {                        // thread t handles feature f=t
        const double v0 = (double)s_red[tid * 4 + 0];
        const double v1 = (double)s_red[tid * 4 + 1];
        const double v2 = (double)s_red[tid * 4 + 2];
        const double v3 = (double)s_red[tid * 4 + 3];
        double pr[10];
        pr[0] = v0 * v0; pr[1] = v1 * v0; pr[2] = v1 * v1;
        pr[3] = v2 * v0; pr[4] = v2 * v1; pr[5] = v2 * v2;
        pr[6] = v3 * v0; pr[7] = v3 * v1; pr[8] = v3 * v2; pr[9] = v3 * v3;
        #pragma unroll
        for (int t = 0; t < 10; ++t) {
            #pragma unroll
            for (int off = 16; off > 0; off >>= 1)
                pr[t] += __shfl_xor_sync(0xffffffffu, pr[t], off);
        }
        if ((tid & 31) == 0) {
            #pragma unroll
            for (int t = 0; t < 10; ++t) s_gram2[tid >> 5][t] = pr[t];
        }
    }
    __syncthreads();
    if (tid < 10) {
        const int unit = side * 128 + b * NKP + kk;
        g_gram[unit][tid] = s_gram2[0][tid] + s_gram2[1][tid];
    }
}

// Compensated product-accumulate: (s,c) += a*b  with TwoProd + Knuth TwoSum.
__device__ __forceinline__ void dot2_acc(float& s, float& cmp, float a, float b)
{
    const float p  = __fmul_rn(a, b);
    const float ep = __fmaf_rn(a, b, -p);          // exact product error
    const float t  = __fadd_rn(s, p);
    const float z  = __fsub_rn(t, s);
    const float e2 = __fadd_rn(__fsub_rn(s, __fsub_rn(t, z)),
                               __fsub_rn(p, z));   // exact sum error (Knuth)
    s   = t;
    cmp = __fadd_rn(cmp, __fadd_rn(ep, e2));
}

// ---------------------------------------------------------------------------
// Kernel 2: grid 256 blocks x 256 threads, 32 pairs per block.
// Phase 1: EIGHT threads/pair (8-feature chunks, Dot2 on S only); exact fp64
//   8-lane butterfly reduction into s_d[16][32] (4 KB).
// Phase 2: warp 0 (32 pairs, packed) runs the fp32 epilogue with fp64 guard;
//   Pg/Ph read from g_gram. Grid > SM count -> ~2 blocks/SM, so one block's
//   fp32 accumulation overlaps the other's fp64/MUFU epilogue tail.
// ---------------------------------------------------------------------------
__global__ void __launch_bounds__(256)
ume_pair_kernel(float* __restrict__ out)
{
    const int bx  = blockIdx.x;          // 0..255
    const int b   = bx >> 7;             // batch
    const int i   = (bx >> 1) & 63;      // source kp
    const int jb  = (bx & 1) * 32;       // target kp base for this block
    const int ja  = threadIdx.x >> 3;    // pair slot 0..31 (accum phase)
    const int sub = threadIdx.x & 7;     // feature-chunk id 0..7

    __shared__ double s_d[16][32];       // 4 KB: 16 S-moments x 32 pairs

    {
        const float4* __restrict__ G = reinterpret_cast<const float4*>(out + OFF_G) + (size_t)(b * NKP + i) * FD;
        const float4* __restrict__ H = reinterpret_cast<const float4*>(out + OFF_H) + (size_t)(b * NKP + jb + ja) * FD;

        float as[16], ac[16];            // Dot2 for S
        #pragma unroll
        for (int t = 0; t < 16; ++t) { as[t] = 0.0f; ac[t] = 0.0f; }

        const int f0 = sub * 8;
        #pragma unroll
        for (int ff = 0; ff < 8; ++ff) {
            const int f = f0 + ff;
            const float4 gr = __ldg(&G[f]);
            const float4 hr = __ldg(&H[f]);
            const float g0 = gr.x, g1 = gr.y, g2 = gr.z, g3 = gr.w;
            const float h0 = hr.x, h1 = hr.y, h2 = hr.z, h3 = hr.w;

            dot2_acc(as[0],  ac[0],  h0, g0); dot2_acc(as[1],  ac[1],  h0, g1);
            dot2_acc(as[2],  ac[2],  h0, g2); dot2_acc(as[3],  ac[3],  h0, g3);
            dot2_acc(as[4],  ac[4],  h1, g0); dot2_acc(as[5],  ac[5],  h1, g1);
            dot2_acc(as[6],  ac[6],  h1, g2); dot2_acc(as[7],  ac[7],  h1, g3);
            dot2_acc(as[8],  ac[8],  h2, g0); dot2_acc(as[9],  ac[9],  h2, g1);
            dot2_acc(as[10], ac[10], h2, g2); dot2_acc(as[11], ac[11], h2, g3);
            dot2_acc(as[12], ac[12], h3, g0); dot2_acc(as[13], ac[13], h3, g1);
            dot2_acc(as[14], ac[14], h3, g2); dot2_acc(as[15], ac[15], h3, g3);
        }

        // exact fp64 reduction across the 8-lane group, deposit to shared
        #pragma unroll
        for (int t = 0; t < 16; ++t) {
            double v = (double)as[t] + (double)ac[t];
            v += __shfl_xor_sync(0xffffffffu, v, 1);
            v += __shfl_xor_sync(0xffffffffu, v, 2);
            v += __shfl_xor_sync(0xffffffffu, v, 4);
            if (sub == 0) s_d[t][ja] = v;
        }
    }
    __syncthreads();

    // ---- Phase 2: packed epilogue on warp 0 --------------------------------
    if (threadIdx.x >= 32) return;
    const int jp   = threadIdx.x;              // pair slot in this block
    const int pair = (b * NKP + i) * NKP + jb + jp;

    double Sm[4][4];
    #pragma unroll
    for (int a = 0; a < 4; ++a)
        #pragma unroll
        for (int bb = 0; bb < 4; ++bb) Sm[a][bb] = s_d[a * 4 + bb][jp];

    // Pg/Ph from precomputed Gram (packed lower triangle)
    const double* __restrict__ PgS = g_gram[b * NKP + i];
    const double* __restrict__ PhS = g_gram[128 + b * NKP + jb + jp];
    double Pg0[4];
    float  Pgf[4][4], Phf[4][4];
    {
        int idx = 0;
        #pragma unroll
        for (int a = 0; a < 4; ++a)
            #pragma unroll
            for (int bb = 0; bb <= a; ++bb) {
                const double vg = PgS[idx];
                const double vh = PhS[idx];
                Pgf[a][bb] = Pgf[bb][a] = (float)vg;
                Phf[a][bb] = Phf[bb][a] = (float)vh;
                if (bb == 0) Pg0[a] = vg;
                ++idx;
            }
    }

    // ---- fp64: wlc/wrc + A (cancellation-sensitive) ------------------------
    const double denl = Pg0[0] + 2e-16;     // mg_sq(+eps) + eps
    const double denr = Sm[0][0] + 1e-16;   // mg_mh + eps
    const double rdenl = 1.0 / denl;
    const double rdenr = 1.0 / denr;
    double wlc[3], wrc[3];
    #pragma unroll
    for (int dd = 0; dd < 3; ++dd) {
        wlc[dd] = Pg0[dd + 1] * rdenl;
        wrc[dd] = Sm[dd + 1][0] * rdenr;
    }

    float A[3][3];
    #pragma unroll
    for (int a = 0; a < 3; ++a)
        #pragma unroll
        for (int bb = 0; bb < 3; ++bb)
            A[a][bb] = (float)(Sm[1 + bb][1 + a] - wrc[bb] * Sm[0][1 + a]
                             - wlc[a] * Sm[1 + bb][0] + wrc[bb] * wlc[a] * Sm[0][0]);

    // ---- fp32 Jacobi eigendecomposition of B = A^T A -> V ------------------
    float B[3][3];
    #pragma unroll
    for (int r = 0; r < 3; ++r)
        #pragma unroll
        for (int cc = 0; cc < 3; ++cc) {
            float s = 0.0f;
            #pragma unroll
            for (int k = 0; k < 3; ++k) s += A[k][r] * A[k][cc];
            B[r][cc] = s;
        }
    float V[3][3] = {{1, 0, 0}, {0, 1, 0}, {0, 0, 1}};
    for (int sweep = 0; sweep < 8; ++sweep) {
        const float off = fabsf(B[0][1]) + fabsf(B[0][2]) + fabsf(B[1][2]);
        const float dia = fabsf(B[0][0]) + fabsf(B[1][1]) + fabsf(B[2][2]) + 1e-30f;
        if (off <= 1e-7f * dia) break;
        #pragma unroll
        for (int pq = 0; pq < 3; ++pq) {
            const int p = (pq == 2) ? 1 : 0;
            const int q = (pq == 0) ? 1 : 2;
            const float bpq = B[p][q];
            if (fabsf(bpq) <= 1e-9f * (fabsf(B[p][p]) + fabsf(B[q][q])))
                continue;
            const float tau = __fdividef(B[q][q] - B[p][p], 2.0f * bpq);
            const float t = ((tau >= 0.0f) ? 1.0f : -1.0f) *
                            __fdividef(1.0f, fabsf(tau) + sqrtf(1.0f + tau * tau));
            const float c = rsqrtf(1.0f + t * t);
            const float s = t * c;
            #pragma unroll
            for (int k = 0; k < 3; ++k) {
                const float bkp = B[k][p], bkq = B[k][q];
                B[k][p] = c * bkp - s * bkq; B[k][q] = s * bkp + c * bkq;
            }
            #pragma unroll
            for (int k = 0; k < 3; ++k) {
                const float bpk = B[p][k], bqk = B[q][k];
                B[p][k] = c * bpk - s * bqk; B[q][k] = s * bpk + c * bqk;
            }
            #pragma unroll
            for (int k = 0; k < 3; ++k) {
                const float vkp = V[k][p], vkq = V[k][q];
                V[k][p] = c * vkp - s * vkq; V[k][q] = s * vkp + c * vkq;
            }
        }
    }
    // sort eigenvalues descending (track permutation)
    int o0 = 0, o1 = 1, o2 = 2;
    {
        float ea = B[0][0], eb = B[1][1], ec = B[2][2];
        if (ea < eb) { int t = o0; o0 = o1; o1 = t; float u = ea; ea = eb; eb = u; }
        if (ea < ec) { int t = o0; o0 = o2; o2 = t; float u = ea; ea = ec; ec = u; }
        if (eb < ec) { int t = o1; o1 = o2; o2 = t; float u = eb; eb = ec; ec = u; }
    }
    const float v0[3] = {V[0][o0], V[1][o0], V[2][o0]};
    const float v1[3] = {V[0][o1], V[1][o1], V[2][o1]};
    const float v2[3] = {v0[1] * v1[2] - v0[2] * v1[1],
                         v0[2] * v1[0] - v0[0] * v1[2],
                         v0[0] * v1[1] - v0[1] * v1[0]};

    float R[3][3] = {{1, 0, 0}, {0, 1, 0}, {0, 0, 1}};
    {
        float u0[3], u1[3];
        #pragma unroll
        for (int r = 0; r < 3; ++r) {
            u0[r] = A[r][0] * v0[0] + A[r][1] * v0[1] + A[r][2] * v0[2];
            u1[r] = A[r][0] * v1[0] + A[r][1] * v1[1] + A[r][2] * v1[2];
        }
        const float n0sq = u0[0] * u0[0] + u0[1] * u0[1] + u0[2] * u0[2];
        if (n0sq > 1e-30f) {
            const float rn0 = rsqrtf(n0sq);
            #pragma unroll
            for (int r = 0; r < 3; ++r) u0[r] *= rn0;
            const float d01 = u0[0] * u1[0] + u0[1] * u1[1] + u0[2] * u1[2];
            #pragma unroll
            for (int r = 0; r < 3; ++r) u1[r] -= d01 * u0[r];
            float n1sq = u1[0] * u1[0] + u1[1] * u1[1] + u1[2] * u1[2];
            if (n1sq > 1e-12f * n0sq) {
                const float rn1 = rsqrtf(n1sq);
                #pragma unroll
                for (int r = 0; r < 3; ++r) u1[r] *= rn1;
            } else {
                float t[3] = {0, 0, 0};
                t[(fabsf(u0[0]) < 0.9f) ? 0 : 1] = 1.0f;
                const float dt = u0[0] * t[0] + u0[1] * t[1] + u0[2] * t[2];
                #pragma unroll
                for (int r = 0; r < 3; ++r) u1[r] = t[r] - dt * u0[r];
                n1sq = u1[0] * u1[0] + u1[1] * u1[1] + u1[2] * u1[2];
                const float rn1 = rsqrtf(n1sq);
                #pragma unroll
                for (int r = 0; r < 3; ++r) u1[r] *= rn1;
            }
            const float u2[3] = {u0[1] * u1[2] - u0[2] * u1[1],
                                 u0[2] * u1[0] - u0[0] * u1[2],
                                 u0[0] * u1[1] - u0[1] * u1[0]};
            // R = u0 v0^T + u1 v1^T + (u0 x u1)(v0 x v1)^T  (sign-invariant Kabsch)
            #pragma unroll
            for (int r = 0; r < 3; ++r)
                #pragma unroll
                for (int cc = 0; cc < 3; ++cc)
                    R[r][cc] = u0[r] * v0[cc] + u1[r] * v1[cc] + u2[r] * v2[cc];
        }
    }

    const float wlcf[3] = {(float)wlc[0], (float)wlc[1], (float)wlc[2]};
    const float wrcf[3] = {(float)wrc[0], (float)wrc[1], (float)wrc[2]};
    float b2[3];
    #pragma unroll
    for (int dd = 0; dd < 3; ++dd)
        b2[dd] = wrcf[dd] - (wlcf[0] * R[0][dd] + wlcf[1] * R[1][dd] + wlcf[2] * R[2][dd]);

    // Write T: rows 0..2 = [R^T | b2], row 3 = [0 0 0 1]
    float* To = out + OFF_T + (size_t)pair * 16;
    #pragma unroll
    for (int r = 0; r < 3; ++r) {
        To[r * 4 + 0] = R[0][r];
        To[r * 4 + 1] = R[1][r];
        To[r * 4 + 2] = R[2][r];
        To[r * 4 + 3] = b2[r];
    }
    To[12] = 0.0f; To[13] = 0.0f; To[14] = 0.0f; To[15] = 1.0f;

    // ---- D (fp32 Cholesky path):
    //   ||Qh Qh^T - Qg Qg^T||_F = sqrt(8 - 2 ||Lg^{-1} S^T Lh^{-T}||_F^2)
    float rLgd[4], rLhd[4];            // reciprocal diagonals
    {
        for (int r = 0; r < 4; ++r)
            for (int cc = 0; cc <= r; ++cc) {
                float vg = Pgf[r][cc], vh = Phf[r][cc];
                for (int k = 0; k < cc; ++k) {
                    vg -= Pgf[r][k] * Pgf[cc][k];
                    vh -= Phf[r][k] * Phf[cc][k];
                }
                if (r == cc) {
                    const float lg = sqrtf(fmaxf(vg, 1e-30f));
                    const float lh = sqrtf(fmaxf(vh, 1e-30f));
                    Pgf[r][r] = lg; rLgd[r] = __fdividef(1.0f, lg);
                    Phf[r][r] = lh; rLhd[r] = __fdividef(1.0f, lh);
                } else {
                    Pgf[r][cc] = vg * rLgd[cc];
                    Phf[r][cc] = vh * rLhd[cc];
                }
            }
    }
    // X = Lg^{-1} S^T   (S^T[r][c] = Sm[c][r])
    float X[4][4];
    for (int cc = 0; cc < 4; ++cc)
        for (int r = 0; r < 4; ++r) {
            float v = (float)Sm[cc][r];
            for (int k = 0; k < r; ++k) v -= Pgf[r][k] * X[k][cc];
            X[r][cc] = v * rLgd[r];
        }
    // Y col c = Lh^{-1} (X^T col c); accumulate ||Y||_F^2
    float fro = 0.0f;
    for (int cc = 0; cc < 4; ++cc) {
        float y[4];
        for (int r = 0; r < 4; ++r) {
            float v = X[cc][r];
            for (int k = 0; k < r; ++k) v -= Phf[r][k] * y[k];
            y[r] = v * rLhd[r];
            fro += y[r] * y[r];
        }
    }
    const float Dv = 0.707f * sqrtf(fmaxf(8.0f - 2.0f * fro, 0.0f));
    out[OFF_D + pair] = Dv;
}

// ---------------------------------------------------------------------------
extern "C" void kernel_launch(void* const* d_in, const int* in_sizes, int n_in,
                              void* d_out, int out_size)
{
    (void)in_sizes; (void)n_in; (void)out_size;
    const float* sp = (const float*)d_in[0];
    const float* sf = (const float*)d_in[1];
    const float* sk = (const float*)d_in[2];
    const float* tp = (const float*)d_in[3];
    const float* tf = (const float*)d_in[4];
    const float* tk = (const float*)d_in[5];
    float* out = (float*)d_out;

    dim3 g1(BSZ * NKP, 2);
    ume_moments_kernel<<<g1, 256>>>(sp, sf, sk, tp, tf, tk, out);

    ume_pair_kernel<<<2 * BSZ * NKP, 256>>>(out);  // 32 pairs/block, 8 thr/pair
}

// round 17
// speedup vs baseline: 1.1235x; 1.1235x over previous
#include <cuda_runtime.h>

// ---------------------------------------------------------------------------
// Problem constants (fixed shapes per reference setup_inputs)
// ---------------------------------------------------------------------------
namespace {
constexpr int NPTS = 16384;
constexpr int BSZ  = 2;
constexpr int NKP  = 64;
constexpr int FD   = 64;
constexpr int KNN  = 64;
constexpr float RAD2 = 2.25f;   // 1.5^2

// Output layout: concat of flattened (T, D, G, H)
constexpr int SZ_T  = BSZ * NKP * NKP * 16;   // 131072
constexpr int SZ_D  = BSZ * NKP * NKP;        // 8192
constexpr int SZ_G  = BSZ * NKP * FD * 4;     // 32768
constexpr int OFF_T = 0;
constexpr int OFF_D = SZ_T;
constexpr int OFF_G = OFF_D + SZ_D;
constexpr int OFF_H = OFF_G + SZ_G;

constexpr int SEG = NPTS / 8;                 // 2048 points per warp segment
}

// Per-unit hoisted epilogue inputs (written by moments kernel):
//   g_chol[unit][0..9]  = fp32 Cholesky L (lower, packed row-major)
//   g_chol[unit][10..13]= fp32 reciprocal diagonals
//   units 0..127 = G side, 128..255 = H side.
//   g_wlc[b*64+kk][0..2] = fp64 wlc (source side only).
__device__ float  g_chol[256][16];
__device__ double g_wlc[128][4];

// ---------------------------------------------------------------------------
// Kernel 1: fused ball-query + moments + Gram/Cholesky/wlc epilogue.
// ---------------------------------------------------------------------------
__global__ void __launch_bounds__(256)
ume_moments_kernel(const float* __restrict__ s_pts, const float* __restrict__ s_ft,
                   const float* __restrict__ s_kp,
                   const float* __restrict__ t_pts, const float* __restrict__ t_ft,
                   const float* __restrict__ t_kp,
                   float* __restrict__ out)
{
    const int side = blockIdx.y;
    const float* pts = side ? t_pts : s_pts;
    const float* ft  = side ? t_ft  : s_ft;
    const float* kp  = side ? t_kp  : s_kp;
    float* gout = out + (side ? OFF_H : OFF_G);

    const int b    = blockIdx.x >> 6;
    const int kk   = blockIdx.x & 63;
    const int tid  = threadIdx.x;
    const int lane = tid & 31;
    const int wid  = tid >> 5;

    const float kx = kp[(b * NKP + kk) * 3 + 0];
    const float ky = kp[(b * NKP + kk) * 3 + 1];
    const float kz = kp[(b * NKP + kk) * 3 + 2];

    __shared__ int    s_wl[8][KNN];    // per-warp ordered hit lists
    __shared__ int    s_wc[8];         // per-warp hit counts (capped at 64)
    __shared__ int    s_idx[KNN];      // merged first-64 (sentinel -1)
    __shared__ float  s_red[256];
    __shared__ float  s_r2[2];
    __shared__ double s_den;
    __shared__ double s_gram2[2][10];

    const float* bp = pts + (size_t)b * NPTS * 3;

    // ---- Phase A: warp-local scan (decoupled ballots) ----------------------
    {
        const int seg0 = wid * SEG;
        int cnt_w = 0;
        const unsigned lt = (1u << lane) - 1u;
        for (int ch = 0; ch < 8; ++ch) {
            if (cnt_w >= KNN) break;
            float px[8], py[8], pz[8];
            #pragma unroll
            for (int u = 0; u < 8; ++u) {
                const int j = seg0 + ch * 256 + u * 32 + lane;
                px[u] = bp[3 * j + 0];
                py[u] = bp[3 * j + 1];
                pz[u] = bp[3 * j + 2];
            }
            unsigned mm[8];
            unsigned myh = 0u;
            #pragma unroll
            for (int u = 0; u < 8; ++u) {
                const float dx = px[u] - kx, dy = py[u] - ky, dz = pz[u] - kz;
                const bool hit = (dx * dx + dy * dy + dz * dz) < RAD2;
                mm[u] = __ballot_sync(0xffffffffu, hit);
                myh |= (hit ? 1u : 0u) << u;
            }
            #pragma unroll
            for (int u = 0; u < 8; ++u) {
                const int j = seg0 + ch * 256 + u * 32 + lane;
                const int pos = cnt_w + __popc(mm[u] & lt);
                if (((myh >> u) & 1u) && pos < KNN) s_wl[wid][pos] = j;
                cnt_w += __popc(mm[u]);
            }
        }
        if (lane == 0) s_wc[wid] = min(cnt_w, KNN);
    }
    __syncthreads();

    // ---- Merge: ordered concat of warp lists, truncated to 64 --------------
    if (tid < KNN) {
        int pre = 0, total = 0;
        #pragma unroll
        for (int ww = 0; ww < 8; ++ww) total += s_wc[ww];
        const int cnt = min(total, KNN);
        int v = -1;
        if (tid < cnt) {
            #pragma unroll
            for (int ww = 0; ww < 8; ++ww) {
                const int c = s_wc[ww];
                if (tid >= pre && tid < pre + c) v = s_wl[ww][tid - pre];
                pre += c;
            }
        }
        s_idx[tid] = v;
    }
    __syncthreads();

    // ---- Phase B: moments, batched gathers (groups of 8), 4 fp64 chains ----
    const int f = tid >> 2;
    const int c = tid & 3;
    const float* bft = ft + (size_t)b * NPTS * FD;

    double a0 = 0.0, a1 = 0.0, a2 = 0.0, a3 = 0.0;
    #pragma unroll 2
    for (int g = 0; g < 8; ++g) {
        int   id8[8];
        float wv[8], pp[8];
        #pragma unroll
        for (int u = 0; u < 8; ++u) id8[u] = s_idx[g * 8 + u];
        #pragma unroll
        for (int u = 0; u < 8; ++u) {
            const bool valid = id8[u] >= 0;
            const int i0 = valid ? id8[u] : 0;
            wv[u] = valid ? bft[(size_t)i0 * FD + f] : 0.0f;
            pp[u] = (c == 0) ? 1.0f : bp[i0 * 3 + (c - 1)];
        }
        a0 += (double)wv[0] * (double)pp[0];
        a1 += (double)wv[1] * (double)pp[1];
        a2 += (double)wv[2] * (double)pp[2];
        a3 += (double)wv[3] * (double)pp[3];
        a0 += (double)wv[4] * (double)pp[4];
        a1 += (double)wv[5] * (double)pp[5];
        a2 += (double)wv[6] * (double)pp[6];
        a3 += (double)wv[7] * (double)pp[7];
    }
    const double acc = (a0 + a1) + (a2 + a3);

    s_red[tid] = (float)acc;
    __syncthreads();
    if (tid < 64) {
        float v = s_red[tid * 4];          // m0[f] values
        #pragma unroll
        for (int off = 16; off > 0; off >>= 1)
            v += __shfl_xor_sync(0xffffffffu, v, off);
        if ((tid & 31) == 0) s_r2[tid >> 5] = v;
    }
    __syncthreads();
    if (tid == 0) s_den = (double)(s_r2[0] + s_r2[1]) + 1e-6;
    __syncthreads();
    const float vnorm = (float)(acc / s_den);
    gout[((size_t)(b * NKP + kk) * FD + f) * 4 + c] = vnorm;

    // ---- Gram epilogue: exact fp64 products, butterfly reduce --------------
    s_red[tid] = vnorm;                    // stage normalized row values
    __syncthreads();
    if (tid < 64) {                        // thread t handles feature f=t
        const double v0 = (double)s_red[tid * 4 + 0];
        const double v1 = (double)s_red[tid * 4 + 1];
        const double v2 = (double)s_red[tid * 4 + 2];
        const double v3 = (double)s_red[tid * 4 + 3];
        double pr[10];
        pr[0] = v0 * v0; pr[1] = v1 * v0; pr[2] = v1 * v1;
        pr[3] = v2 * v0; pr[4] = v2 * v1; pr[5] = v2 * v2;
        pr[6] = v3 * v0; pr[7] = v3 * v1; pr[8] = v3 * v2; pr[9] = v3 * v3;
        #pragma unroll
        for (int t = 0; t < 10; ++t) {
            #pragma unroll
            for (int off = 16; off > 0; off >>= 1)
                pr[t] += __shfl_xor_sync(0xffffffffu, pr[t], off);
        }
        if ((tid & 31) == 0) {
            #pragma unroll
            for (int t = 0; t < 10; ++t) s_gram2[tid >> 5][t] = pr[t];
        }
    }
    __syncthreads();

    // ---- Hoisted per-unit epilogue: fp32 Cholesky (+ fp64 wlc for G side) --
    if (tid == 0) {
        const int unit = side * 128 + b * NKP + kk;
        double gram[10];
        #pragma unroll
        for (int t = 0; t < 10; ++t) gram[t] = s_gram2[0][t] + s_gram2[1][t];

        // fp32 copy (same cast the pair epilogue used before)
        float P[4][4];
        {
            int idx = 0;
            #pragma unroll
            for (int a = 0; a < 4; ++a)
                #pragma unroll
                for (int bb = 0; bb <= a; ++bb) {
                    P[a][bb] = P[bb][a] = (float)gram[idx];
                    ++idx;
                }
        }
        float rD[4];
        for (int r = 0; r < 4; ++r)
            for (int cc = 0; cc <= r; ++cc) {
                float v = P[r][cc];
                for (int k = 0; k < cc; ++k) v -= P[r][k] * P[cc][k];
                if (r == cc) {
                    const float l = sqrtf(fmaxf(v, 1e-30f));
                    P[r][r] = l; rD[r] = __fdividef(1.0f, l);
                } else {
                    P[r][cc] = v * rD[cc];
                }
            }
        // store packed L + recip diag
        {
            int idx = 0;
            #pragma unroll
            for (int a = 0; a < 4; ++a)
                #pragma unroll
                for (int bb = 0; bb <= a; ++bb) { g_chol[unit][idx] = P[a][bb]; ++idx; }
            #pragma unroll
            for (int a = 0; a < 4; ++a) g_chol[unit][10 + a] = rD[a];
        }
        // wlc for source side (fp64, same formula the pair epilogue used)
        if (side == 0) {
            const double denl = gram[0] + 2e-16;
            const double rdenl = 1.0 / denl;
            g_wlc[b * NKP + kk][0] = gram[1] * rdenl;   // Pg[1][0]
            g_wlc[b * NKP + kk][1] = gram[3] * rdenl;   // Pg[2][0]
            g_wlc[b * NKP + kk][2] = gram[6] * rdenl;   // Pg[3][0]
        }
    }
}

// Compensated product-accumulate: (s,c) += a*b  with TwoProd + Knuth TwoSum.
__device__ __forceinline__ void dot2_acc(float& s, float& cmp, float a, float b)
{
    const float p  = __fmul_rn(a, b);
    const float ep = __fmaf_rn(a, b, -p);          // exact product error
    const float t  = __fadd_rn(s, p);
    const float z  = __fsub_rn(t, s);
    const float e2 = __fadd_rn(__fsub_rn(s, __fsub_rn(t, z)),
                               __fsub_rn(p, z));   // exact sum error (Knuth)
    s   = t;
    cmp = __fadd_rn(cmp, __fadd_rn(ep, e2));
}

// ---------------------------------------------------------------------------
// Kernel 2 (R15 shape, proven 20.8us): block = 256 threads, 64 pairs/block,
// grid 128. Phase 1: 4 threads/pair, Dot2 on S only, exact fp64 4-lane
// reduction into s_d[16][64]. Phase 2: threads 0..63 packed epilogue; wlc
// and Cholesky factors of Pg/Ph read precomputed from g_wlc / g_chol.
// ---------------------------------------------------------------------------
__global__ void __launch_bounds__(256)
ume_pair_kernel(float* __restrict__ out)
{
    const int b   = blockIdx.x >> 6;
    const int i   = blockIdx.x & 63;     // source kp
    const int j   = threadIdx.x >> 2;    // target kp (0..63)
    const int sub = threadIdx.x & 3;     // feature-chunk id (0..3)

    __shared__ double s_d[16][64];       // 8 KB: 16 S-moments x 64 pairs

    {
        const float4* __restrict__ G = reinterpret_cast<const float4*>(out + OFF_G) + (size_t)(b * NKP + i) * FD;
        const float4* __restrict__ H = reinterpret_cast<const float4*>(out + OFF_H) + (size_t)(b * NKP + j) * FD;

        float as[16], ac[16];            // Dot2 for S
        #pragma unroll
        for (int t = 0; t < 16; ++t) { as[t] = 0.0f; ac[t] = 0.0f; }

        const int f0 = sub * 16;
        #pragma unroll 4
        for (int ff = 0; ff < 16; ++ff) {
            const int f = f0 + ff;
            const float4 gr = __ldg(&G[f]);
            const float4 hr = __ldg(&H[f]);
            const float g0 = gr.x, g1 = gr.y, g2 = gr.z, g3 = gr.w;
            const float h0 = hr.x, h1 = hr.y, h2 = hr.z, h3 = hr.w;

            dot2_acc(as[0],  ac[0],  h0, g0); dot2_acc(as[1],  ac[1],  h0, g1);
            dot2_acc(as[2],  ac[2],  h0, g2); dot2_acc(as[3],  ac[3],  h0, g3);
            dot2_acc(as[4],  ac[4],  h1, g0); dot2_acc(as[5],  ac[5],  h1, g1);
            dot2_acc(as[6],  ac[6],  h1, g2); dot2_acc(as[7],  ac[7],  h1, g3);
            dot2_acc(as[8],  ac[8],  h2, g0); dot2_acc(as[9],  ac[9],  h2, g1);
            dot2_acc(as[10], ac[10], h2, g2); dot2_acc(as[11], ac[11], h2, g3);
            dot2_acc(as[12], ac[12], h3, g0); dot2_acc(as[13], ac[13], h3, g1);
            dot2_acc(as[14], ac[14], h3, g2); dot2_acc(as[15], ac[15], h3, g3);
        }

        // exact fp64 reduction across the 4-lane group, deposit to shared
        #pragma unroll
        for (int t = 0; t < 16; ++t) {
            double v = (double)as[t] + (double)ac[t];
            v += __shfl_xor_sync(0xffffffffu, v, 1);
            v += __shfl_xor_sync(0xffffffffu, v, 2);
            if (sub == 0) s_d[t][j] = v;
        }
    }
    __syncthreads();

    // ---- Phase 2: packed epilogue on warps 0-1 -----------------------------
    if (threadIdx.x >= 64) return;
    const int jp   = threadIdx.x;              // pair slot in this block
    const int pair = (blockIdx.x << 6) + jp;

    double Sm[4][4];
    #pragma unroll
    for (int a = 0; a < 4; ++a)
        #pragma unroll
        for (int bb = 0; bb < 4; ++bb) Sm[a][bb] = s_d[a * 4 + bb][jp];

    // Hoisted per-unit data
    const double* __restrict__ Wl = g_wlc[b * NKP + i];
    const float*  __restrict__ Cg = g_chol[b * NKP + i];
    const float*  __restrict__ Ch = g_chol[128 + b * NKP + jp];

    double wlc[3];
    wlc[0] = Wl[0]; wlc[1] = Wl[1]; wlc[2] = Wl[2];

    const double denr = Sm[0][0] + 1e-16;   // mg_mh + eps
    const double rdenr = 1.0 / denr;
    double wrc[3];
    #pragma unroll
    for (int dd = 0; dd < 3; ++dd) wrc[dd] = Sm[dd + 1][0] * rdenr;

    float A[3][3];
    #pragma unroll
    for (int a = 0; a < 3; ++a)
        #pragma unroll
        for (int bb = 0; bb < 3; ++bb)
            A[a][bb] = (float)(Sm[1 + bb][1 + a] - wrc[bb] * Sm[0][1 + a]
                             - wlc[a] * Sm[1 + bb][0] + wrc[bb] * wlc[a] * Sm[0][0]);

    // ---- fp32 Jacobi eigendecomposition of B = A^T A -> V ------------------
    float B[3][3];
    #pragma unroll
    for (int r = 0; r < 3; ++r)
        #pragma unroll
        for (int cc = 0; cc < 3; ++cc) {
            float s = 0.0f;
            #pragma unroll
            for (int k = 0; k < 3; ++k) s += A[k][r] * A[k][cc];
            B[r][cc] = s;
        }
    float V[3][3] = {{1, 0, 0}, {0, 1, 0}, {0, 0, 1}};
    for (int sweep = 0; sweep < 8; ++sweep) {
        const float off = fabsf(B[0][1]) + fabsf(B[0][2]) + fabsf(B[1][2]);
        const float dia = fabsf(B[0][0]) + fabsf(B[1][1]) + fabsf(B[2][2]) + 1e-30f;
        if (off <= 1e-7f * dia) break;
        #pragma unroll
        for (int pq = 0; pq < 3; ++pq) {
            const int p = (pq == 2) ? 1 : 0;
            const int q = (pq == 0) ? 1 : 2;
            const float bpq = B[p][q];
            if (fabsf(bpq) <= 1e-9f * (fabsf(B[p][p]) + fabsf(B[q][q])))
                continue;
            const float tau = __fdividef(B[q][q] - B[p][p], 2.0f * bpq);
            const float t = ((tau >= 0.0f) ? 1.0f : -1.0f) *
                            __fdividef(1.0f, fabsf(tau) + sqrtf(1.0f + tau * tau));
            const float c = rsqrtf(1.0f + t * t);
            const float s = t * c;
            #pragma unroll
            for (int k = 0; k < 3; ++k) {
                const float bkp = B[k][p], bkq = B[k][q];
                B[k][p] = c * bkp - s * bkq; B[k][q] = s * bkp + c * bkq;
            }
            #pragma unroll
            for (int k = 0; k < 3; ++k) {
                const float bpk = B[p][k], bqk = B[q][k];
                B[p][k] = c * bpk - s * bqk; B[q][k] = s * bpk + c * bqk;
            }
            #pragma unroll
            for (int k = 0; k < 3; ++k) {
                const float vkp = V[k][p], vkq = V[k][q];
                V[k][p] = c * vkp - s * vkq; V[k][q] = s * vkp + c * vkq;
            }
        }
    }
    // sort eigenvalues descending (track permutation)
    int o0 = 0, o1 = 1, o2 = 2;
    {
        float ea = B[0][0], eb = B[1][1], ec = B[2][2];
        if (ea < eb) { int t = o0; o0 = o1; o1 = t; float u = ea; ea = eb; eb = u; }
        if (ea < ec) { int t = o0; o0 = o2; o2 = t; float u = ea; ea = ec; ec = u; }
        if (eb < ec) { int t = o1; o1 = o2; o2 = t; float u = eb; eb = ec; ec = u; }
    }
    const float v0[3] = {V[0][o0], V[1][o0], V[2][o0]};
    const float v1[3] = {V[0][o1], V[1][o1], V[2][o1]};
    const float v2[3] = {v0[1] * v1[2] - v0[2] * v1[1],
                         v0[2] * v1[0] - v0[0] * v1[2],
                         v0[0] * v1[1] - v0[1] * v1[0]};

    float R[3][3] = {{1, 0, 0}, {0, 1, 0}, {0, 0, 1}};
    {
        float u0[3], u1[3];
        #pragma unroll
        for (int r = 0; r < 3; ++r) {
            u0[r] = A[r][0] * v0[0] + A[r][1] * v0[1] + A[r][2] * v0[2];
            u1[r] = A[r][0] * v1[0] + A[r][1] * v1[1] + A[r][2] * v1[2];
        }
        const float n0sq = u0[0] * u0[0] + u0[1] * u0[1] + u0[2] * u0[2];
        if (n0sq > 1e-30f) {
            const float rn0 = rsqrtf(n0sq);
            #pragma unroll
            for (int r = 0; r < 3; ++r) u0[r] *= rn0;
            const float d01 = u0[0] * u1[0] + u0[1] * u1[1] + u0[2] * u1[2];
            #pragma unroll
            for (int r = 0; r < 3; ++r) u1[r] -= d01 * u0[r];
            float n1sq = u1[0] * u1[0] + u1[1] * u1[1] + u1[2] * u1[2];
            if (n1sq > 1e-12f * n0sq) {
                const float rn1 = rsqrtf(n1sq);
                #pragma unroll
                for (int r = 0; r < 3; ++r) u1[r] *= rn1;
            } else {
                float t[3] = {0, 0, 0};
                t[(fabsf(u0[0]) < 0.9f) ? 0 : 1] = 1.0f;
                const float dt = u0[0] * t[0] + u0[1] * t[1] + u0[2] * t[2];
                #pragma unroll
                for (int r = 0; r < 3; ++r) u1[r] = t[r] - dt * u0[r];
                n1sq = u1[0] * u1[0] + u1[1] * u1[1] + u1[2] * u1[2];
                const float rn1 = rsqrtf(n1sq);
                #pragma unroll
                for (int r = 0; r < 3; ++r) u1[r] *= rn1;
            }
            const float u2[3] = {u0[1] * u1[2] - u0[2] * u1[1],
                                 u0[2] * u1[0] - u0[0] * u1[2],
                                 u0[0] * u1[1] - u0[1] * u1[0]};
            // R = u0 v0^T + u1 v1^T + (u0 x u1)(v0 x v1)^T  (sign-invariant Kabsch)
            #pragma unroll
            for (int r = 0; r < 3; ++r)
                #pragma unroll
                for (int cc = 0; cc < 3; ++cc)
                    R[r][cc] = u0[r] * v0[cc] + u1[r] * v1[cc] + u2[r] * v2[cc];
        }
    }

    const float wlcf[3] = {(float)wlc[0], (float)wlc[1], (float)wlc[2]};
    const float wrcf[3] = {(float)wrc[0], (float)wrc[1], (float)wrc[2]};
    float b2[3];
    #pragma unroll
    for (int dd = 0; dd < 3; ++dd)
        b2[dd] = wrcf[dd] - (wlcf[0] * R[0][dd] + wlcf[1] * R[1][dd] + wlcf[2] * R[2][dd]);

    // Write T: rows 0..2 = [R^T | b2], row 3 = [0 0 0 1]
    float* To = out + OFF_T + (size_t)pair * 16;
    #pragma unroll
    for (int r = 0; r < 3; ++r) {
        To[r * 4 + 0] = R[0][r];
        To[r * 4 + 1] = R[1][r];
        To[r * 4 + 2] = R[2][r];
        To[r * 4 + 3] = b2[r];
    }
    To[12] = 0.0f; To[13] = 0.0f; To[14] = 0.0f; To[15] = 1.0f;

    // ---- D (fp32 Cholesky solves with precomputed factors):
    //   ||Qh Qh^T - Qg Qg^T||_F = sqrt(8 - 2 ||Lg^{-1} S^T Lh^{-T}||_F^2)
    float Lg[4][4], Lh[4][4], rLgd[4], rLhd[4];
    {
        int idx = 0;
        #pragma unroll
        for (int a = 0; a < 4; ++a)
            #pragma unroll
            for (int bb = 0; bb <= a; ++bb) {
                Lg[a][bb] = Cg[idx];
                Lh[a][bb] = Ch[idx];
                ++idx;
            }
        #pragma unroll
        for (int a = 0; a < 4; ++a) { rLgd[a] = Cg[10 + a]; rLhd[a] = Ch[10 + a]; }
    }
    // X = Lg^{-1} S^T   (S^T[r][c] = Sm[c][r])
    float X[4][4];
    for (int cc = 0; cc < 4; ++cc)
        for (int r = 0; r < 4; ++r) {
            float v = (float)Sm[cc][r];
            for (int k = 0; k < r; ++k) v -= Lg[r][k] * X[k][cc];
            X[r][cc] = v * rLgd[r];
        }
    // Y col c = Lh^{-1} (X^T col c); accumulate ||Y||_F^2
    float fro = 0.0f;
    for (int cc = 0; cc < 4; ++cc) {
        float y[4];
        for (int r = 0; r < 4; ++r) {
            float v = X[cc][r];
            for (int k = 0; k < r; ++k) v -= Lh[r][k] * y[k];
            y[r] = v * rLhd[r];
            fro += y[r] * y[r];
        }
    }
    const float Dv = 0.707f * sqrtf(fmaxf(8.0f - 2.0f * fro, 0.0f));
    out[OFF_D + pair] = Dv;
}

// ---------------------------------------------------------------------------
extern "C" void kernel_launch(void* const* d_in, const int* in_sizes, int n_in,
                              void* d_out, int out_size)
{
    (void)in_sizes; (void)n_in; (void)out_size;
    const float* sp = (const float*)d_in[0];
    const float* sf = (const float*)d_in[1];
    const float* sk = (const float*)d_in[2];
    const float* tp = (const float*)d_in[3];
    const float* tf = (const float*)d_in[4];
    const float* tk = (const float*)d_in[5];
    float* out = (float*)d_out;

    dim3 g1(BSZ * NKP, 2);
    ume_moments_kernel<<<g1, 256>>>(sp, sf, sk, tp, tf, tk, out);

    ume_pair_kernel<<<BSZ * NKP, 256>>>(out);  // R15 shape + hoisted chol/wlc
}